// round 6
// baseline (speedup 1.0000x reference)
#include <cuda_runtime.h>
#include <cuda_bf16.h>
#include <cstdint>

#define Bsz 4
#define Tsz 4096
#define Isz 1024
#define Esz 16
#define Ksz 512
#define Jsz 1024

// ---------------- scratch: pre-split operands ----------------
__device__ __nv_bfloat16 g_WhiT[(size_t)Esz * Jsz * Isz];   // W^T [E][J][I]
__device__ __nv_bfloat16 g_WloT[(size_t)Esz * Jsz * Isz];
__device__ __nv_bfloat16 g_Xhi[(size_t)Bsz * Tsz * Isz];    // X   [B][T][I]
__device__ __nv_bfloat16 g_Xlo[(size_t)Bsz * Tsz * Isz];

// ---------------- helpers ----------------
__device__ __forceinline__ uint32_t smem_u32(const void* p) {
    uint32_t a;
    asm("{ .reg .u64 t; cvta.to.shared.u64 t, %1; cvt.u32.u64 %0, t; }" : "=r"(a) : "l"(p));
    return a;
}
// 64B rows of 4x16B chunks; chunk xor'd by ((row>>1)&3): conflict-free STS/ldsm.
__device__ __forceinline__ uint32_t swzoff(int row, int c) {
    return (uint32_t)(row * 64 + ((c ^ ((row >> 1) & 3)) * 16));
}
__device__ __forceinline__ void ldsm4(uint32_t* r, uint32_t addr) {
    asm volatile("ldmatrix.sync.aligned.m8n8.x4.shared.b16 {%0,%1,%2,%3}, [%4];"
                 : "=r"(r[0]), "=r"(r[1]), "=r"(r[2]), "=r"(r[3]) : "r"(addr));
}
__device__ __forceinline__ void mma16816(float* d, const uint32_t* a, const uint32_t* b) {
    asm volatile("mma.sync.aligned.m16n8k16.row.col.f32.bf16.bf16.f32 "
                 "{%0,%1,%2,%3},{%4,%5,%6,%7},{%8,%9},{%0,%1,%2,%3};"
                 : "+f"(d[0]), "+f"(d[1]), "+f"(d[2]), "+f"(d[3])
                 : "r"(a[0]), "r"(a[1]), "r"(a[2]), "r"(a[3]), "r"(b[0]), "r"(b[1]));
}
__device__ __forceinline__ void cpasync16(uint32_t dst, const void* src) {
    asm volatile("cp.async.cg.shared.global [%0], [%1], 16;" :: "r"(dst), "l"(src));
}

// ---------------- pre-pass 1: W [E][I][J] fp32 -> W^T hi/lo bf16 [E][J][I] ----------------
__global__ void w_split_transpose(const float* __restrict__ W) {
    __shared__ float tile[32][33];
    const int e = blockIdx.z;
    const int i0 = blockIdx.y * 32, j0 = blockIdx.x * 32;
    const int tx = threadIdx.x, ty = threadIdx.y;   // 32 x 8
    const float* Wp = W + ((size_t)e * Isz + i0) * Jsz + j0;
    #pragma unroll
    for (int r = 0; r < 4; r++)
        tile[ty + 8 * r][tx] = Wp[(size_t)(ty + 8 * r) * Jsz + tx];
    __syncthreads();
    const size_t ob = ((size_t)e * Jsz + j0) * Isz + i0;
    #pragma unroll
    for (int r = 0; r < 4; r++) {
        const int j = ty + 8 * r;
        const float x = tile[tx][j];
        const __nv_bfloat16 h = __float2bfloat16(x);
        const float hf = __bfloat162float(h);
        const __nv_bfloat16 l = __float2bfloat16(x - hf);
        g_WhiT[ob + (size_t)j * Isz + tx] = h;
        g_WloT[ob + (size_t)j * Isz + tx] = l;
    }
}

// ---------------- pre-pass 2: X fp32 -> hi/lo bf16 ----------------
__global__ void x_split(const float* __restrict__ X) {
    const size_t i = ((size_t)blockIdx.x * blockDim.x + threadIdx.x) * 4;
    const float4 v = *(const float4*)(X + i);
    __nv_bfloat162 h01 = __floats2bfloat162_rn(v.x, v.y);
    __nv_bfloat162 h23 = __floats2bfloat162_rn(v.z, v.w);
    const float2 f01 = __bfloat1622float2(h01);
    const float2 f23 = __bfloat1622float2(h23);
    __nv_bfloat162 l01 = __floats2bfloat162_rn(v.x - f01.x, v.y - f01.y);
    __nv_bfloat162 l23 = __floats2bfloat162_rn(v.z - f23.x, v.w - f23.y);
    uint2 hh = make_uint2(*(uint32_t*)&h01, *(uint32_t*)&h23);
    uint2 ll = make_uint2(*(uint32_t*)&l01, *(uint32_t*)&l23);
    *(uint2*)(g_Xhi + i) = hh;
    *(uint2*)(g_Xlo + i) = ll;
}

// ---------------- main: 256x128 tile, bf16x3, 4-stage cp.async ----------------
#define NT 256
#define STAGE 49152
#define NSTG 4
// per stage: A_HI @0 (16KB), A_LO @16384, B_HI @32768 (8KB), B_LO @40960
#define SMEM_BYTES (NSTG * STAGE + 1024)

__global__ __launch_bounds__(NT, 1)
void moe_gemm(const int* __restrict__ ind, float* __restrict__ Y) {
    extern __shared__ char sm[];
    const uint32_t sbase = smem_u32(sm);
    int* rows = (int*)(sm + NSTG * STAGE);

    const int tid = threadIdx.x;
    const int be = blockIdx.z, b = be >> 4, e = be & 15;
    const int m0 = blockIdx.y * 256, n0 = blockIdx.x * 128;

    rows[tid] = ind[((size_t)b * Esz + e) * Ksz + m0 + tid];
    __syncthreads();

    // ---- producer mapping
    // A: thread t -> gathered row t, all 4 chunks, hi+lo (8 cp.async)
    const uint32_t offA0 = swzoff(tid, 0);
    const uint32_t offA1 = swzoff(tid, 1);
    const uint32_t offA2 = swzoff(tid, 2);
    const uint32_t offA3 = swzoff(tid, 3);
    const size_t xoff = ((size_t)b * Tsz + rows[tid]) * Isz;
    const __nv_bfloat16* xh = g_Xhi + xoff;
    const __nv_bfloat16* xl = g_Xlo + xoff;
    // B: thread t -> row t>>1, chunks {2(t&1), 2(t&1)+1}, hi+lo (4 cp.async)
    const int bn  = tid >> 1;
    const int bc0 = (tid & 1) * 2;
    const uint32_t offB0 = swzoff(bn, bc0);
    const uint32_t offB1 = swzoff(bn, bc0 + 1);
    const size_t woff = ((size_t)e * Jsz + n0 + bn) * Isz + bc0 * 8;
    const __nv_bfloat16* wh = g_WhiT + woff;
    const __nv_bfloat16* wl = g_WloT + woff;

    // ---- consumer mapping (warp tile 64x64): 4 M-warps x 2 N-warps
    const int lane = tid & 31, w = tid >> 5;
    const int wm = (w & 3) * 64, wn = (w >> 2) * 64;
    uint32_t loffA[4], loffB[4];
    {
        const int chiA = lane >> 4;
        #pragma unroll
        for (int mt = 0; mt < 4; ++mt) {
            const int rowA = wm + mt * 16 + (lane & 7) + ((lane >> 3) & 1) * 8;
            loffA[mt] = swzoff(rowA, chiA);
        }
        const int chiB = (lane >> 3) & 1;
        #pragma unroll
        for (int ng = 0; ng < 4; ++ng) {
            const int rowB = wn + ng * 16 + (lane & 7) + ((lane >> 4) & 1) * 8;
            loffB[ng] = swzoff(rowB, chiB);
        }
    }

    float acc[4][8][4];
    #pragma unroll
    for (int i = 0; i < 4; ++i)
        #pragma unroll
        for (int j = 0; j < 8; ++j)
            #pragma unroll
            for (int q = 0; q < 4; ++q) acc[i][j][q] = 0.0f;

    auto issue = [&](int c) {
        const uint32_t stg = sbase + (uint32_t)(c & (NSTG - 1)) * STAGE;
        const int k0 = c * 32;
        cpasync16(stg + offA0,         xh + k0);
        cpasync16(stg + offA1,         xh + k0 + 8);
        cpasync16(stg + offA2,         xh + k0 + 16);
        cpasync16(stg + offA3,         xh + k0 + 24);
        cpasync16(stg + 16384 + offA0, xl + k0);
        cpasync16(stg + 16384 + offA1, xl + k0 + 8);
        cpasync16(stg + 16384 + offA2, xl + k0 + 16);
        cpasync16(stg + 16384 + offA3, xl + k0 + 24);
        cpasync16(stg + 32768 + offB0, wh + k0);
        cpasync16(stg + 32768 + offB1, wh + k0 + 8);
        cpasync16(stg + 40960 + offB0, wl + k0);
        cpasync16(stg + 40960 + offB1, wl + k0 + 8);
    };

    #pragma unroll
    for (int s = 0; s < NSTG - 1; ++s) {
        issue(s);
        asm volatile("cp.async.commit_group;" ::: "memory");
    }

    for (int c = 0; c < 32; ++c) {
        asm volatile("cp.async.wait_group %0;" :: "n"(NSTG - 2) : "memory");
        __syncthreads();   // all warps done with compute c-1; stage (c+3)&3 free; stage c ready

        if (c + NSTG - 1 < 32) issue(c + NSTG - 1);
        asm volatile("cp.async.commit_group;" ::: "memory");

        const uint32_t stg = sbase + (uint32_t)(c & (NSTG - 1)) * STAGE;

        #pragma unroll
        for (int ks = 0; ks < 2; ++ks) {
            const uint32_t kx = (uint32_t)ks << 5;
            uint32_t ah[4][4], al_[4][4], bh[4][4], bl[4][4];
            #pragma unroll
            for (int mt = 0; mt < 4; ++mt) {
                ldsm4(ah[mt],  stg +         (loffA[mt] ^ kx));
                ldsm4(al_[mt], stg + 16384 + (loffA[mt] ^ kx));
            }
            #pragma unroll
            for (int ng = 0; ng < 4; ++ng) {
                ldsm4(bh[ng], stg + 32768 + (loffB[ng] ^ kx));
                ldsm4(bl[ng], stg + 40960 + (loffB[ng] ^ kx));
            }
            #pragma unroll
            for (int mt = 0; mt < 4; ++mt)
                #pragma unroll
                for (int ng = 0; ng < 4; ++ng) {
                    mma16816(acc[mt][2 * ng],     ah[mt],  bh[ng]);
                    mma16816(acc[mt][2 * ng + 1], ah[mt],  bh[ng] + 2);
                    mma16816(acc[mt][2 * ng],     ah[mt],  bl[ng]);
                    mma16816(acc[mt][2 * ng + 1], ah[mt],  bl[ng] + 2);
                    mma16816(acc[mt][2 * ng],     al_[mt], bh[ng]);
                    mma16816(acc[mt][2 * ng + 1], al_[mt], bh[ng] + 2);
                }
        }
    }

    // ---- epilogue
    float* Yb = Y + ((size_t)be * Ksz + m0) * Jsz + n0;
    #pragma unroll
    for (int mt = 0; mt < 4; ++mt) {
        const int row = wm + mt * 16 + (lane >> 2);
        #pragma unroll
        for (int j = 0; j < 8; ++j) {
            const int col = wn + j * 8 + (lane & 3) * 2;
            float2 v0 = make_float2(acc[mt][j][0], acc[mt][j][1]);
            float2 v1 = make_float2(acc[mt][j][2], acc[mt][j][3]);
            *(float2*)&Yb[(size_t)row * Jsz + col] = v0;
            *(float2*)&Yb[(size_t)(row + 8) * Jsz + col] = v1;
        }
    }
}

// ---------------- launch ----------------
extern "C" void kernel_launch(void* const* d_in, const int* in_sizes, int n_in,
                              void* d_out, int out_size) {
    const float* X   = (const float*)d_in[0];
    const int*   ind = (const int*)d_in[1];
    const float* W   = (const float*)d_in[2];
    float*       Y   = (float*)d_out;

    cudaFuncSetAttribute(moe_gemm, cudaFuncAttributeMaxDynamicSharedMemorySize, SMEM_BYTES);

    dim3 pgrid(Jsz / 32, Isz / 32, Esz);
    w_split_transpose<<<pgrid, dim3(32, 8)>>>(W);
    x_split<<<(Bsz * Tsz * Isz) / (256 * 4), 256>>>(X);

    dim3 grid(Jsz / 128, Ksz / 256, Bsz * Esz);   // (8, 2, 64) = 1024 CTAs
    moe_gemm<<<grid, NT, SMEM_BYTES>>>(ind, Y);
}

// round 7
// speedup vs baseline: 1.3069x; 1.3069x over previous
#include <cuda_runtime.h>
#include <cuda_bf16.h>
#include <cstdint>

#define Bsz 4
#define Tsz 4096
#define Isz 1024
#define Esz 16
#define Ksz 512
#define Jsz 1024

// ---------------- scratch: pre-split operands ----------------
__device__ __nv_bfloat16 g_WhiT[(size_t)Esz * Jsz * Isz];   // W^T [E][J][I]
__device__ __nv_bfloat16 g_WloT[(size_t)Esz * Jsz * Isz];
__device__ __nv_bfloat16 g_Xhi[(size_t)Bsz * Tsz * Isz];    // X   [B][T][I]
__device__ __nv_bfloat16 g_Xlo[(size_t)Bsz * Tsz * Isz];

// ---------------- helpers ----------------
__device__ __forceinline__ uint32_t smem_u32(const void* p) {
    uint32_t a;
    asm("{ .reg .u64 t; cvta.to.shared.u64 t, %1; cvt.u32.u64 %0, t; }" : "=r"(a) : "l"(p));
    return a;
}
// 64B rows of 4x16B chunks; chunk xor'd by ((row>>1)&3): conflict-free STS/ldsm.
__device__ __forceinline__ uint32_t swzoff(int row, int c) {
    return (uint32_t)(row * 64 + ((c ^ ((row >> 1) & 3)) * 16));
}
__device__ __forceinline__ void ldsm4(uint32_t* r, uint32_t addr) {
    asm volatile("ldmatrix.sync.aligned.m8n8.x4.shared.b16 {%0,%1,%2,%3}, [%4];"
                 : "=r"(r[0]), "=r"(r[1]), "=r"(r[2]), "=r"(r[3]) : "r"(addr));
}
__device__ __forceinline__ void mma16816(float* d, const uint32_t* a, const uint32_t* b) {
    asm volatile("mma.sync.aligned.m16n8k16.row.col.f32.bf16.bf16.f32 "
                 "{%0,%1,%2,%3},{%4,%5,%6,%7},{%8,%9},{%0,%1,%2,%3};"
                 : "+f"(d[0]), "+f"(d[1]), "+f"(d[2]), "+f"(d[3])
                 : "r"(a[0]), "r"(a[1]), "r"(a[2]), "r"(a[3]), "r"(b[0]), "r"(b[1]));
}
__device__ __forceinline__ void cpasync16(uint32_t dst, const void* src) {
    asm volatile("cp.async.cg.shared.global [%0], [%1], 16;" :: "r"(dst), "l"(src));
}

// ---------------- pre-pass 1: W [E][I][J] fp32 -> W^T hi/lo bf16 [E][J][I] ----------------
__global__ void w_split_transpose(const float* __restrict__ W) {
    __shared__ float tile[32][33];
    const int e = blockIdx.z;
    const int i0 = blockIdx.y * 32, j0 = blockIdx.x * 32;
    const int tx = threadIdx.x, ty = threadIdx.y;   // 32 x 8
    const float* Wp = W + ((size_t)e * Isz + i0) * Jsz + j0;
    #pragma unroll
    for (int r = 0; r < 4; r++)
        tile[ty + 8 * r][tx] = Wp[(size_t)(ty + 8 * r) * Jsz + tx];
    __syncthreads();
    const size_t ob = ((size_t)e * Jsz + j0) * Isz + i0;
    #pragma unroll
    for (int r = 0; r < 4; r++) {
        const int j = ty + 8 * r;
        const float x = tile[tx][j];
        const __nv_bfloat16 h = __float2bfloat16(x);
        const float hf = __bfloat162float(h);
        const __nv_bfloat16 l = __float2bfloat16(x - hf);
        g_WhiT[ob + (size_t)j * Isz + tx] = h;
        g_WloT[ob + (size_t)j * Isz + tx] = l;
    }
}

// ---------------- pre-pass 2: X fp32 -> hi/lo bf16 ----------------
__global__ void x_split(const float* __restrict__ X) {
    const size_t i = ((size_t)blockIdx.x * blockDim.x + threadIdx.x) * 4;
    const float4 v = *(const float4*)(X + i);
    __nv_bfloat162 h01 = __floats2bfloat162_rn(v.x, v.y);
    __nv_bfloat162 h23 = __floats2bfloat162_rn(v.z, v.w);
    const float2 f01 = __bfloat1622float2(h01);
    const float2 f23 = __bfloat1622float2(h23);
    __nv_bfloat162 l01 = __floats2bfloat162_rn(v.x - f01.x, v.y - f01.y);
    __nv_bfloat162 l23 = __floats2bfloat162_rn(v.z - f23.x, v.w - f23.y);
    uint2 hh = make_uint2(*(uint32_t*)&h01, *(uint32_t*)&h23);
    uint2 ll = make_uint2(*(uint32_t*)&l01, *(uint32_t*)&l23);
    *(uint2*)(g_Xhi + i) = hh;
    *(uint2*)(g_Xlo + i) = ll;
}

// ---------------- main: 128x128 tile, 512 threads, warp tile 32x32 ----------------
#define NT 512
#define STAGE 32768
#define NSTG 4
// per stage: A_HI @0 (8KB), A_LO @8192, B_HI @16384, B_LO @24576
#define SMEM_BYTES (NSTG * STAGE + 1024)

__global__ __launch_bounds__(NT, 1)
void moe_gemm(const int* __restrict__ ind, float* __restrict__ Y) {
    extern __shared__ char sm[];
    const uint32_t sbase = smem_u32(sm);
    int* rows = (int*)(sm + NSTG * STAGE);

    const int tid = threadIdx.x;
    const int be = blockIdx.z, b = be >> 4, e = be & 15;
    const int m0 = blockIdx.y * 128, n0 = blockIdx.x * 128;

    if (tid < 128) rows[tid] = ind[((size_t)b * Esz + e) * Ksz + m0 + tid];
    __syncthreads();

    // ---- producer mapping: thread t -> row t>>2, chunk t&3 (1 x 16B each for
    //      A_hi, A_lo, B_hi, B_lo = 4 cp.async per thread per stage)
    const int prow = tid >> 2;
    const int pc   = tid & 3;
    const uint32_t poff = swzoff(prow, pc);
    const size_t xoff = ((size_t)b * Tsz + rows[prow]) * Isz + pc * 8;
    const __nv_bfloat16* xh = g_Xhi + xoff;
    const __nv_bfloat16* xl = g_Xlo + xoff;
    const size_t woff = ((size_t)e * Jsz + n0 + prow) * Isz + pc * 8;
    const __nv_bfloat16* wh = g_WhiT + woff;
    const __nv_bfloat16* wl = g_WloT + woff;

    // ---- consumer mapping (warp tile 32x32): 4 M-warps x 4 N-warps
    const int lane = tid & 31, w = tid >> 5;
    const int wm = (w & 3) * 32, wn = (w >> 2) * 32;
    uint32_t loffA[2], loffB[2];
    {
        const int chiA = lane >> 4;
        #pragma unroll
        for (int mt = 0; mt < 2; ++mt) {
            const int rowA = wm + mt * 16 + (lane & 7) + ((lane >> 3) & 1) * 8;
            loffA[mt] = swzoff(rowA, chiA);
        }
        const int chiB = (lane >> 3) & 1;
        #pragma unroll
        for (int ng = 0; ng < 2; ++ng) {
            const int rowB = wn + ng * 16 + (lane & 7) + ((lane >> 4) & 1) * 8;
            loffB[ng] = swzoff(rowB, chiB);
        }
    }

    float acc[2][4][4];
    #pragma unroll
    for (int i = 0; i < 2; ++i)
        #pragma unroll
        for (int j = 0; j < 4; ++j)
            #pragma unroll
            for (int q = 0; q < 4; ++q) acc[i][j][q] = 0.0f;

    auto issue = [&](int c) {
        const uint32_t stg = sbase + (uint32_t)(c & (NSTG - 1)) * STAGE;
        const int k0 = c * 32;
        cpasync16(stg + poff,         xh + k0);
        cpasync16(stg + 8192  + poff, xl + k0);
        cpasync16(stg + 16384 + poff, wh + k0);
        cpasync16(stg + 24576 + poff, wl + k0);
    };

    #pragma unroll
    for (int s = 0; s < NSTG - 1; ++s) {
        issue(s);
        asm volatile("cp.async.commit_group;" ::: "memory");
    }

    for (int c = 0; c < 32; ++c) {
        asm volatile("cp.async.wait_group %0;" :: "n"(NSTG - 2) : "memory");
        __syncthreads();   // compute(c-1) done everywhere; stage (c+3)&3 is free; stage c ready

        if (c + NSTG - 1 < 32) issue(c + NSTG - 1);
        asm volatile("cp.async.commit_group;" ::: "memory");

        const uint32_t stg = sbase + (uint32_t)(c & (NSTG - 1)) * STAGE;

        #pragma unroll
        for (int ks = 0; ks < 2; ++ks) {
            const uint32_t kx = (uint32_t)ks << 5;
            uint32_t ah[2][4], al_[2][4], bh[2][4], bl[2][4];
            #pragma unroll
            for (int mt = 0; mt < 2; ++mt) {
                ldsm4(ah[mt],  stg +        (loffA[mt] ^ kx));
                ldsm4(al_[mt], stg + 8192 + (loffA[mt] ^ kx));
            }
            #pragma unroll
            for (int ng = 0; ng < 2; ++ng) {
                ldsm4(bh[ng], stg + 16384 + (loffB[ng] ^ kx));
                ldsm4(bl[ng], stg + 24576 + (loffB[ng] ^ kx));
            }
            #pragma unroll
            for (int mt = 0; mt < 2; ++mt)
                #pragma unroll
                for (int ng = 0; ng < 2; ++ng) {
                    mma16816(acc[mt][2 * ng],     ah[mt],  bh[ng]);
                    mma16816(acc[mt][2 * ng + 1], ah[mt],  bh[ng] + 2);
                    mma16816(acc[mt][2 * ng],     ah[mt],  bl[ng]);
                    mma16816(acc[mt][2 * ng + 1], ah[mt],  bl[ng] + 2);
                    mma16816(acc[mt][2 * ng],     al_[mt], bh[ng]);
                    mma16816(acc[mt][2 * ng + 1], al_[mt], bh[ng] + 2);
                }
        }
    }

    // ---- epilogue
    float* Yb = Y + ((size_t)be * Ksz + m0) * Jsz + n0;
    #pragma unroll
    for (int mt = 0; mt < 2; ++mt) {
        const int row = wm + mt * 16 + (lane >> 2);
        #pragma unroll
        for (int j = 0; j < 4; ++j) {
            const int col = wn + j * 8 + (lane & 3) * 2;
            float2 v0 = make_float2(acc[mt][j][0], acc[mt][j][1]);
            float2 v1 = make_float2(acc[mt][j][2], acc[mt][j][3]);
            *(float2*)&Yb[(size_t)row * Jsz + col] = v0;
            *(float2*)&Yb[(size_t)(row + 8) * Jsz + col] = v1;
        }
    }
}

// ---------------- launch ----------------
extern "C" void kernel_launch(void* const* d_in, const int* in_sizes, int n_in,
                              void* d_out, int out_size) {
    const float* X   = (const float*)d_in[0];
    const int*   ind = (const int*)d_in[1];
    const float* W   = (const float*)d_in[2];
    float*       Y   = (float*)d_out;

    cudaFuncSetAttribute(moe_gemm, cudaFuncAttributeMaxDynamicSharedMemorySize, SMEM_BYTES);

    dim3 pgrid(Jsz / 32, Isz / 32, Esz);
    w_split_transpose<<<pgrid, dim3(32, 8)>>>(W);
    x_split<<<(Bsz * Tsz * Isz) / (256 * 4), 256>>>(X);

    dim3 grid(Jsz / 128, Ksz / 128, Bsz * Esz);   // (8, 4, 64) = 2048 CTAs
    moe_gemm<<<grid, NT, SMEM_BYTES>>>(ind, Y);
}

// round 8
// speedup vs baseline: 1.3713x; 1.0493x over previous
#include <cuda_runtime.h>
#include <cstdint>

#define Bsz 4
#define Tsz 4096
#define Isz 1024
#define Esz 16
#define Ksz 512
#define Jsz 1024

// ---------------- scratch: tf32-rounded, pair-interleaved operands ----------------
// Within each k8 group, columns stored as [k0,k4,k1,k5,k2,k6,k3,k7] so an
// mma fragment pair (c, c+4) is 8 contiguous bytes (one LDS.64).
__device__ float g_Wt[(size_t)Esz * Jsz * Isz];   // W^T [E][J][I]
__device__ float g_Xt[(size_t)Bsz * Tsz * Isz];   // X   [B][T][I]

// ---------------- helpers ----------------
__device__ __forceinline__ uint32_t smem_u32(const void* p) {
    uint32_t a;
    asm("{ .reg .u64 t; cvta.to.shared.u64 t, %1; cvt.u32.u64 %0, t; }" : "=r"(a) : "l"(p));
    return a;
}
__device__ __forceinline__ uint32_t tf32r(float x) {   // round-to-nearest tf32, as bits
    uint32_t y;
    asm("cvt.rna.tf32.f32 %0, %1;" : "=r"(y) : "f"(x));
    return y;
}
__device__ __forceinline__ uint2 lds64(uint32_t addr) {
    uint2 v;
    asm volatile("ld.shared.v2.b32 {%0,%1}, [%2];" : "=r"(v.x), "=r"(v.y) : "r"(addr));
    return v;
}
__device__ __forceinline__ void mma_tf32(float* d, uint32_t a0, uint32_t a1, uint32_t a2,
                                         uint32_t a3, uint32_t b0, uint32_t b1) {
    asm volatile("mma.sync.aligned.m16n8k8.row.col.f32.tf32.tf32.f32 "
                 "{%0,%1,%2,%3},{%4,%5,%6,%7},{%8,%9},{%0,%1,%2,%3};"
                 : "+f"(d[0]), "+f"(d[1]), "+f"(d[2]), "+f"(d[3])
                 : "r"(a0), "r"(a1), "r"(a2), "r"(a3), "r"(b0), "r"(b1));
}
__device__ __forceinline__ void cpasync16(uint32_t dst, const void* src) {
    asm volatile("cp.async.cg.shared.global [%0], [%1], 16;" :: "r"(dst), "l"(src));
}
// chunk swizzle: row r, 16B chunk Q (0..7 per 128B row)
__device__ __forceinline__ uint32_t Fsw(int r, int Q) {
    return (uint32_t)(2 * (((Q >> 1) ^ (r & 3))) + (Q & 1));
}

// ---------------- pre-pass 1: W [E][I][J] -> W^T tf32 interleaved [E][J][I] ----------------
__global__ void w_cvt(const float* __restrict__ W) {
    __shared__ float tile[32][33];
    const int e = blockIdx.z;
    const int i0 = blockIdx.y * 32, j0 = blockIdx.x * 32;
    const int tx = threadIdx.x, ty = threadIdx.y;   // 32 x 8
    const float* Wp = W + ((size_t)e * Isz + i0) * Jsz + j0;
    #pragma unroll
    for (int r = 0; r < 4; r++)
        tile[ty + 8 * r][tx] = Wp[(size_t)(ty + 8 * r) * Jsz + tx];
    __syncthreads();
    const size_t ob = ((size_t)e * Jsz + j0) * Isz + i0;
    const int c = tx & 7;
    const int iperm = (tx & ~7) + (c & 3) * 2 + (c >> 2);
    uint32_t* out = (uint32_t*)g_Wt;
    #pragma unroll
    for (int r = 0; r < 4; r++) {
        const int j = ty + 8 * r;
        out[ob + (size_t)j * Isz + iperm] = tf32r(tile[tx][j]);
    }
}

// ---------------- pre-pass 2: X -> tf32 interleaved ----------------
__global__ void x_cvt(const float* __restrict__ X) {
    const size_t base = ((size_t)blockIdx.x * blockDim.x + threadIdx.x) * 8;
    const float4 v0 = *(const float4*)(X + base);      // c0..c3
    const float4 v1 = *(const float4*)(X + base + 4);  // c4..c7
    uint4 o0 = make_uint4(tf32r(v0.x), tf32r(v1.x), tf32r(v0.y), tf32r(v1.y));
    uint4 o1 = make_uint4(tf32r(v0.z), tf32r(v1.z), tf32r(v0.w), tf32r(v1.w));
    *(uint4*)((uint32_t*)g_Xt + base)     = o0;
    *(uint4*)((uint32_t*)g_Xt + base + 4) = o1;
}

// ---------------- main: 128x256 tile, tf32 1-pass, 512 threads ----------------
#define NT 512
#define STAGE 49152            // A: 16KB @0, B: 32KB @16384
#define NSTG 4
#define SMEM_BYTES (NSTG * STAGE + 1024)

__global__ __launch_bounds__(NT, 1)
void moe_gemm(const int* __restrict__ ind, float* __restrict__ Y) {
    extern __shared__ char sm[];
    const uint32_t sbase = smem_u32(sm);
    int* rows = (int*)(sm + NSTG * STAGE);

    const int tid = threadIdx.x;
    const int be = blockIdx.z, b = be >> 4, e = be & 15;
    const int m0 = blockIdx.y * 128, n0 = blockIdx.x * 256;

    if (tid < 128) rows[tid] = ind[((size_t)b * Esz + e) * Ksz + m0 + tid];
    __syncthreads();

    // ---- producer: A = 2 chunks/thread, B = 4 chunks/thread
    const int arow = tid >> 2;
    const int aq   = (tid & 3) * 2;
    const uint32_t adst = (uint32_t)(arow * 128) + Fsw(arow, aq) * 16;  // F(aq+1)=F(aq)+1
    const float* asrc = g_Xt + ((size_t)b * Tsz + rows[arow]) * Isz + aq * 4;

    const int brow = tid >> 1;
    const int bq   = (tid & 1) * 4;
    uint32_t bdst[4];
    #pragma unroll
    for (int j = 0; j < 4; ++j)
        bdst[j] = 16384u + (uint32_t)(brow * 128) + Fsw(brow, bq + j) * 16;
    const float* bsrc = g_Wt + ((size_t)e * Jsz + n0 + brow) * Isz + bq * 4;

    // ---- consumer: warp tile 32x64 (4 M-warps x 4 N-warps)
    const int lane = tid & 31, w = tid >> 5;
    const int wm = (w & 3) * 32, wn = (w >> 2) * 64;
    const int rA = lane >> 2;
    const int xorA = rA & 3;
    const uint32_t lo = (uint32_t)(((lane & 3) >> 1) * 16 + (lane & 1) * 8);
    uint32_t aoff[2], boff[8];
    #pragma unroll
    for (int mt = 0; mt < 2; ++mt) aoff[mt] = (uint32_t)((wm + mt * 16 + rA) * 128) + lo;
    #pragma unroll
    for (int ng = 0; ng < 8; ++ng) boff[ng] = 16384u + (uint32_t)((wn + ng * 8 + rA) * 128) + lo;

    float acc[2][8][4];
    #pragma unroll
    for (int i = 0; i < 2; ++i)
        #pragma unroll
        for (int j = 0; j < 8; ++j)
            #pragma unroll
            for (int q = 0; q < 4; ++q) acc[i][j][q] = 0.0f;

    auto issue = [&](int c) {
        const uint32_t stg = sbase + (uint32_t)(c & (NSTG - 1)) * STAGE;
        const int k0 = c * 32;
        cpasync16(stg + adst,      asrc + k0);
        cpasync16(stg + adst + 16, asrc + k0 + 4);
        #pragma unroll
        for (int j = 0; j < 4; ++j)
            cpasync16(stg + bdst[j], bsrc + k0 + 4 * j);
    };

    #pragma unroll
    for (int s = 0; s < NSTG - 1; ++s) {
        issue(s);
        asm volatile("cp.async.commit_group;" ::: "memory");
    }

    for (int c = 0; c < 32; ++c) {
        asm volatile("cp.async.wait_group %0;" :: "n"(NSTG - 2) : "memory");
        __syncthreads();

        if (c + NSTG - 1 < 32) issue(c + NSTG - 1);
        asm volatile("cp.async.commit_group;" ::: "memory");

        const uint32_t stg = sbase + (uint32_t)(c & (NSTG - 1)) * STAGE;

        #pragma unroll
        for (int s = 0; s < 4; ++s) {
            const uint32_t soff = 32u * (uint32_t)(s ^ xorA);
            uint2 a0  = lds64(stg + aoff[0] + soff);
            uint2 a0h = lds64(stg + aoff[0] + soff + 1024);
            uint2 a1  = lds64(stg + aoff[1] + soff);
            uint2 a1h = lds64(stg + aoff[1] + soff + 1024);
            uint2 bf[8];
            #pragma unroll
            for (int ng = 0; ng < 8; ++ng) bf[ng] = lds64(stg + boff[ng] + soff);
            #pragma unroll
            for (int ng = 0; ng < 8; ++ng) {
                mma_tf32(acc[0][ng], a0.x, a0h.x, a0.y, a0h.y, bf[ng].x, bf[ng].y);
                mma_tf32(acc[1][ng], a1.x, a1h.x, a1.y, a1h.y, bf[ng].x, bf[ng].y);
            }
        }
    }

    // ---- epilogue
    float* Yb = Y + ((size_t)be * Ksz + m0) * Jsz + n0;
    #pragma unroll
    for (int mt = 0; mt < 2; ++mt) {
        const int row = wm + mt * 16 + (lane >> 2);
        #pragma unroll
        for (int ng = 0; ng < 8; ++ng) {
            const int col = wn + ng * 8 + (lane & 3) * 2;
            *(float2*)&Yb[(size_t)row * Jsz + col] =
                make_float2(acc[mt][ng][0], acc[mt][ng][1]);
            *(float2*)&Yb[(size_t)(row + 8) * Jsz + col] =
                make_float2(acc[mt][ng][2], acc[mt][ng][3]);
        }
    }
}

// ---------------- launch ----------------
extern "C" void kernel_launch(void* const* d_in, const int* in_sizes, int n_in,
                              void* d_out, int out_size) {
    const float* X   = (const float*)d_in[0];
    const int*   ind = (const int*)d_in[1];
    const float* W   = (const float*)d_in[2];
    float*       Y   = (float*)d_out;

    cudaFuncSetAttribute(moe_gemm, cudaFuncAttributeMaxDynamicSharedMemorySize, SMEM_BYTES);

    dim3 pgrid(Jsz / 32, Isz / 32, Esz);
    w_cvt<<<pgrid, dim3(32, 8)>>>(W);
    x_cvt<<<(Bsz * Tsz * Isz) / (256 * 8), 256>>>(X);

    dim3 grid(Jsz / 256, Ksz / 128, Bsz * Esz);   // (4, 4, 64) = 1024 CTAs
    moe_gemm<<<grid, NT, SMEM_BYTES>>>(ind, Y);
}

// round 9
// speedup vs baseline: 3.1114x; 2.2689x over previous
#include <cuda_runtime.h>
#include <cuda_fp16.h>
#include <cstdint>

#define Bsz 4
#define Tsz 4096
#define Isz 1024
#define Esz 16
#define Ksz 512
#define Jsz 1024

// ---------------- scratch: fp16 operands ----------------
__device__ __half g_WhT[(size_t)Esz * Jsz * Isz];   // W^T [E][J][I]
__device__ __half g_Xh[(size_t)Bsz * Tsz * Isz];    // X   [B][T][I]

// ---------------- helpers ----------------
__device__ __forceinline__ uint32_t smem_u32(const void* p) {
    uint32_t a;
    asm("{ .reg .u64 t; cvta.to.shared.u64 t, %1; cvt.u32.u64 %0, t; }" : "=r"(a) : "l"(p));
    return a;
}
// 64B rows of 4x16B chunks; chunk xor'd by ((row>>1)&3): conflict-free STS/ldsm.
__device__ __forceinline__ uint32_t swzoff(int row, int c) {
    return (uint32_t)(row * 64 + ((c ^ ((row >> 1) & 3)) * 16));
}
__device__ __forceinline__ void ldsm4(uint32_t* r, uint32_t addr) {
    asm volatile("ldmatrix.sync.aligned.m8n8.x4.shared.b16 {%0,%1,%2,%3}, [%4];"
                 : "=r"(r[0]), "=r"(r[1]), "=r"(r[2]), "=r"(r[3]) : "r"(addr));
}
__device__ __forceinline__ void mma16816(float* d, const uint32_t* a, const uint32_t* b) {
    asm volatile("mma.sync.aligned.m16n8k16.row.col.f32.f16.f16.f32 "
                 "{%0,%1,%2,%3},{%4,%5,%6,%7},{%8,%9},{%0,%1,%2,%3};"
                 : "+f"(d[0]), "+f"(d[1]), "+f"(d[2]), "+f"(d[3])
                 : "r"(a[0]), "r"(a[1]), "r"(a[2]), "r"(a[3]), "r"(b[0]), "r"(b[1]));
}
__device__ __forceinline__ void cpasync16(uint32_t dst, const void* src) {
    asm volatile("cp.async.cg.shared.global [%0], [%1], 16;" :: "r"(dst), "l"(src));
}

// ---------------- pre-pass 1: W [E][I][J] fp32 -> W^T fp16 [E][J][I] ----------------
__global__ void w_cvt(const float* __restrict__ W) {
    __shared__ float tile[32][33];
    const int e = blockIdx.z;
    const int i0 = blockIdx.y * 32, j0 = blockIdx.x * 32;
    const int tx = threadIdx.x, ty = threadIdx.y;   // 32 x 8
    const float* Wp = W + ((size_t)e * Isz + i0) * Jsz + j0;
    #pragma unroll
    for (int r = 0; r < 4; r++)
        tile[ty + 8 * r][tx] = Wp[(size_t)(ty + 8 * r) * Jsz + tx];
    __syncthreads();
    const size_t ob = ((size_t)e * Jsz + j0) * Isz + i0;
    #pragma unroll
    for (int r = 0; r < 4; r++) {
        const int j = ty + 8 * r;
        g_WhT[ob + (size_t)j * Isz + tx] = __float2half_rn(tile[tx][j]);
    }
}

// ---------------- pre-pass 2: X fp32 -> fp16 ----------------
__global__ void x_cvt(const float* __restrict__ X) {
    const size_t i = ((size_t)blockIdx.x * blockDim.x + threadIdx.x) * 8;
    const float4 v0 = *(const float4*)(X + i);
    const float4 v1 = *(const float4*)(X + i + 4);
    __half2 h0 = __floats2half2_rn(v0.x, v0.y);
    __half2 h1 = __floats2half2_rn(v0.z, v0.w);
    __half2 h2 = __floats2half2_rn(v1.x, v1.y);
    __half2 h3 = __floats2half2_rn(v1.z, v1.w);
    uint4 o = make_uint4(*(uint32_t*)&h0, *(uint32_t*)&h1, *(uint32_t*)&h2, *(uint32_t*)&h3);
    *(uint4*)(g_Xh + i) = o;
}

// ---------------- main: 128x256 tile, fp16 1-pass, 512 threads ----------------
#define NT 512
#define STAGE 24576           // A @0 (8KB), B @8192 (16KB)
#define NSTG 4
#define SMEM_BYTES (NSTG * STAGE + 1024)

__global__ __launch_bounds__(NT, 1)
void moe_gemm(const int* __restrict__ ind, float* __restrict__ Y) {
    extern __shared__ char sm[];
    const uint32_t sbase = smem_u32(sm);
    int* rows = (int*)(sm + NSTG * STAGE);

    const int tid = threadIdx.x;
    const int be = blockIdx.z, b = be >> 4, e = be & 15;
    const int m0 = blockIdx.y * 128, n0 = blockIdx.x * 256;

    if (tid < 128) rows[tid] = ind[((size_t)b * Esz + e) * Ksz + m0 + tid];
    __syncthreads();

    // ---- producer mapping
    // A: 128 rows x 4 chunks = 512 tasks -> 1 cp.async/thread
    const int arow = tid >> 2;
    const int aq   = tid & 3;
    const uint32_t aoffp = swzoff(arow, aq);
    const __half* xsrc = g_Xh + ((size_t)b * Tsz + rows[arow]) * Isz + aq * 8;
    // B: 256 rows x 4 chunks = 1024 tasks -> 2 cp.async/thread
    const int brow = tid >> 1;
    const int bq0  = (tid & 1) * 2;
    const uint32_t boffp0 = swzoff(brow, bq0);
    const uint32_t boffp1 = swzoff(brow, bq0 + 1);
    const __half* wsrc = g_WhT + ((size_t)e * Jsz + n0 + brow) * Isz + bq0 * 8;

    // ---- consumer mapping (warp tile 32x64): 4 M-warps x 4 N-warps
    const int lane = tid & 31, w = tid >> 5;
    const int wm = (w & 3) * 32, wn = (w >> 2) * 64;
    uint32_t loffA[2], loffB[4];
    {
        const int chiA = lane >> 4;
        #pragma unroll
        for (int mt = 0; mt < 2; ++mt) {
            const int rowA = wm + mt * 16 + (lane & 7) + ((lane >> 3) & 1) * 8;
            loffA[mt] = swzoff(rowA, chiA);
        }
        const int chiB = (lane >> 3) & 1;
        #pragma unroll
        for (int ng = 0; ng < 4; ++ng) {
            const int rowB = wn + ng * 16 + (lane & 7) + ((lane >> 4) & 1) * 8;
            loffB[ng] = swzoff(rowB, chiB);
        }
    }

    float acc[2][8][4];
    #pragma unroll
    for (int i = 0; i < 2; ++i)
        #pragma unroll
        for (int j = 0; j < 8; ++j)
            #pragma unroll
            for (int q = 0; q < 4; ++q) acc[i][j][q] = 0.0f;

    auto issue = [&](int c) {
        const uint32_t stg = sbase + (uint32_t)(c & (NSTG - 1)) * STAGE;
        const int k0 = c * 32;
        cpasync16(stg + aoffp,          xsrc + k0);
        cpasync16(stg + 8192 + boffp0,  wsrc + k0);
        cpasync16(stg + 8192 + boffp1,  wsrc + k0 + 8);
    };

    #pragma unroll
    for (int s = 0; s < NSTG - 1; ++s) {
        issue(s);
        asm volatile("cp.async.commit_group;" ::: "memory");
    }

    for (int c = 0; c < 32; ++c) {
        asm volatile("cp.async.wait_group %0;" :: "n"(NSTG - 2) : "memory");
        __syncthreads();

        if (c + NSTG - 1 < 32) issue(c + NSTG - 1);
        asm volatile("cp.async.commit_group;" ::: "memory");

        const uint32_t stg = sbase + (uint32_t)(c & (NSTG - 1)) * STAGE;

        #pragma unroll
        for (int ks = 0; ks < 2; ++ks) {
            const uint32_t kx = (uint32_t)ks << 5;
            uint32_t a[2][4], bb[4][4];
            #pragma unroll
            for (int mt = 0; mt < 2; ++mt)
                ldsm4(a[mt], stg + (loffA[mt] ^ kx));
            #pragma unroll
            for (int ng = 0; ng < 4; ++ng)
                ldsm4(bb[ng], stg + 8192 + (loffB[ng] ^ kx));
            #pragma unroll
            for (int mt = 0; mt < 2; ++mt)
                #pragma unroll
                for (int ng = 0; ng < 4; ++ng) {
                    mma16816(acc[mt][2 * ng],     a[mt], bb[ng]);
                    mma16816(acc[mt][2 * ng + 1], a[mt], bb[ng] + 2);
                }
        }
    }

    // ---- epilogue
    float* Yb = Y + ((size_t)be * Ksz + m0) * Jsz + n0;
    #pragma unroll
    for (int mt = 0; mt < 2; ++mt) {
        const int row = wm + mt * 16 + (lane >> 2);
        #pragma unroll
        for (int j = 0; j < 8; ++j) {
            const int col = wn + j * 8 + (lane & 3) * 2;
            *(float2*)&Yb[(size_t)row * Jsz + col] =
                make_float2(acc[mt][j][0], acc[mt][j][1]);
            *(float2*)&Yb[(size_t)(row + 8) * Jsz + col] =
                make_float2(acc[mt][j][2], acc[mt][j][3]);
        }
    }
}

// ---------------- launch ----------------
extern "C" void kernel_launch(void* const* d_in, const int* in_sizes, int n_in,
                              void* d_out, int out_size) {
    const float* X   = (const float*)d_in[0];
    const int*   ind = (const int*)d_in[1];
    const float* W   = (const float*)d_in[2];
    float*       Y   = (float*)d_out;

    cudaFuncSetAttribute(moe_gemm, cudaFuncAttributeMaxDynamicSharedMemorySize, SMEM_BYTES);

    dim3 pgrid(Jsz / 32, Isz / 32, Esz);
    w_cvt<<<pgrid, dim3(32, 8)>>>(W);
    x_cvt<<<(Bsz * Tsz * Isz) / (256 * 8), 256>>>(X);

    dim3 grid(Jsz / 256, Ksz / 128, Bsz * Esz);   // (4, 4, 64) = 1024 CTAs
    moe_gemm<<<grid, NT, SMEM_BYTES>>>(ind, Y);
}